// round 7
// baseline (speedup 1.0000x reference)
#include <cuda_runtime.h>
#include <cuda_bf16.h>
#include <cstdint>

#define BATCH 512
#define FEAT  512
#define NBLK  128

#define AS_STR 520                       // 512 + 8 bf16 pad
#define AS_BYTES (64 * AS_STR * 2)       // 66560
#define BS_BYTES (32 * AS_STR * 2)       // 33280
#define SMEM_TOTAL (AS_BYTES + BS_BYTES) // 99840

__device__ float g_S[BATCH * BATCH];
__device__ unsigned g_ctr  = 0;
__device__ volatile unsigned g_epoch = 0;
__device__ unsigned long long g_sum = 0;
__device__ unsigned g_done = 0;

#define SCALE_F 1073741824.0f            // 2^30 fixed-point scale
#define INV_SCALE (1.0 / 1073741824.0)

__global__ void __launch_bounds__(256, 1) fused_kernel(const float* __restrict__ fs,
                                                       const float* __restrict__ ft,
                                                       float* __restrict__ out) {
    extern __shared__ __align__(16) char smem[];
    __nv_bfloat16 (*As)[AS_STR] = (__nv_bfloat16(*)[AS_STR])smem;
    __nv_bfloat16 (*Bs)[AS_STR] = (__nv_bfloat16(*)[AS_STR])(smem + AS_BYTES);

    __shared__ float refs[4][8];
    __shared__ float wr[8][8];
    __shared__ unsigned ep0_sm;

    const int tid   = threadIdx.x;
    const int bid   = blockIdx.y * 16 + blockIdx.x;
    const int mTile = blockIdx.y * 64;
    const int nTile = blockIdx.x * 32;
    const int warp  = tid >> 5;
    const int lane  = tid & 31;
    const int wm    = warp & 3;
    const int wn    = warp >> 2;

    if (tid == 0) ep0_sm = g_epoch;

    // ================= Stage A and B tiles (fp32 -> bf16), high MLP ==========
    {
        const float4* ag = (const float4*)(fs + mTile * FEAT);
        #pragma unroll 16
        for (int v = 0; v < 32; v++) {
            const int idx = tid + v * 256;
            const int row = idx >> 7, c4 = idx & 127;
            const float4 x = ag[row * 128 + c4];
            __nv_bfloat162 h0 = __floats2bfloat162_rn(x.x, x.y);
            __nv_bfloat162 h1 = __floats2bfloat162_rn(x.z, x.w);
            uint2 pk = make_uint2(*(uint32_t*)&h0, *(uint32_t*)&h1);
            *(uint2*)&As[row][c4 * 4] = pk;
        }
        const float4* bg = (const float4*)(ft + nTile * FEAT);
        #pragma unroll 16
        for (int v = 0; v < 16; v++) {
            const int idx = tid + v * 256;
            const int row = idx >> 7, c4 = idx & 127;
            const float4 x = bg[row * 128 + c4];
            __nv_bfloat162 h0 = __floats2bfloat162_rn(x.x, x.y);
            __nv_bfloat162 h1 = __floats2bfloat162_rn(x.z, x.w);
            uint2 pk = make_uint2(*(uint32_t*)&h0, *(uint32_t*)&h1);
            *(uint2*)&Bs[row][c4 * 4] = pk;
        }
    }
    __syncthreads();

    // ================= Mainloop: 32 k-steps, 4 independent MMA chains ========
    float acc0[2][4] = {};   // k in [0,256)
    float acc1[2][4] = {};   // k in [256,512)
    const int a_row = 16 * wm + (lane & 7) + ((lane >> 3) & 1) * 8;
    const int a_k8  = (lane >> 4) * 8;
    const int b_row = 16 * wn + (lane & 7) + (lane >> 4) * 8;
    const int b_k8  = ((lane >> 3) & 1) * 8;

    const uint32_t abase = (uint32_t)__cvta_generic_to_shared(&As[a_row][a_k8]);
    const uint32_t bbase = (uint32_t)__cvta_generic_to_shared(&Bs[b_row][b_k8]);

    #pragma unroll
    for (int kk = 0; kk < 16; kk++) {
        #pragma unroll
        for (int h = 0; h < 2; h++) {
            const uint32_t koff = (kk + h * 16) * 32;   // bytes
            float (*acc)[4] = h ? acc1 : acc0;
            uint32_t a0, a1, a2, a3, b0, b1, b2, b3;
            asm volatile("ldmatrix.sync.aligned.m8n8.x4.shared.b16 {%0,%1,%2,%3}, [%4];\n"
                         : "=r"(a0), "=r"(a1), "=r"(a2), "=r"(a3) : "r"(abase + koff));
            asm volatile("ldmatrix.sync.aligned.m8n8.x4.shared.b16 {%0,%1,%2,%3}, [%4];\n"
                         : "=r"(b0), "=r"(b1), "=r"(b2), "=r"(b3) : "r"(bbase + koff));
            asm volatile("mma.sync.aligned.m16n8k16.row.col.f32.bf16.bf16.f32 "
                         "{%0,%1,%2,%3}, {%4,%5,%6,%7}, {%8,%9}, {%0,%1,%2,%3};\n"
                         : "+f"(acc[0][0]), "+f"(acc[0][1]), "+f"(acc[0][2]), "+f"(acc[0][3])
                         : "r"(a0), "r"(a1), "r"(a2), "r"(a3), "r"(b0), "r"(b1));
            asm volatile("mma.sync.aligned.m16n8k16.row.col.f32.bf16.bf16.f32 "
                         "{%0,%1,%2,%3}, {%4,%5,%6,%7}, {%8,%9}, {%0,%1,%2,%3};\n"
                         : "+f"(acc[1][0]), "+f"(acc[1][1]), "+f"(acc[1][2]), "+f"(acc[1][3])
                         : "r"(a0), "r"(a1), "r"(a2), "r"(a3), "r"(b2), "r"(b3));
        }
    }

    // ================= Epilogue: combine halves, write S tile ================
    {
        const int g = lane >> 2, t = lane & 3;
        const int row0 = mTile + 16 * wm + g;
        #pragma unroll
        for (int h = 0; h < 2; h++) {
            const int col = nTile + 16 * wn + 8 * h + t * 2;
            *(float2*)&g_S[row0 * BATCH + col] =
                make_float2(acc0[h][0] + acc1[h][0], acc0[h][1] + acc1[h][1]);
            *(float2*)&g_S[(row0 + 8) * BATCH + col] =
                make_float2(acc0[h][2] + acc1[h][2], acc0[h][3] + acc1[h][3]);
        }
    }
    __syncthreads();

    // ================= Grid barrier (epoch-based) =============================
    if (tid == 0) {
        __threadfence();
        const unsigned ep0 = ep0_sm;
        const unsigned prev = atomicAdd(&g_ctr, 1);
        if (prev == NBLK - 1) {
            g_ctr = 0;
            __threadfence();
            g_epoch = ep0 + 1;
        } else {
            while (g_epoch == ep0) {}
        }
        __threadfence();
    }
    __syncthreads();

    // ================= Phase 2: 4 rows per block ==============================
    const int row_l = tid >> 6;
    const int c     = tid & 63;
    const int r     = bid * 4 + row_l;
    const float4* S4 = (const float4*)(g_S + r * BATCH);
    const float4 v1 = S4[c];
    const float4 v2 = S4[c + 64];

    const int b0c = r & ~7;
    const int rc0 = b0c >> 2;
    if (rc0 < 64) {
        if (c == rc0)      *(float4*)&refs[row_l][0] = v1;
        if (c == rc0 + 1)  *(float4*)&refs[row_l][4] = v1;
    } else {
        if (c == rc0 - 64) *(float4*)&refs[row_l][0] = v2;
        if (c == rc0 - 63) *(float4*)&refs[row_l][4] = v2;
    }
    __syncthreads();

    float p[8];
    #pragma unroll
    for (int j = 0; j < 8; j++) p[j] = refs[row_l][j];

    float s8[8];
    #pragma unroll
    for (int j = 0; j < 8; j++) {
        s8[j] = fmaxf(v1.x - p[j], 0.f) + fmaxf(v1.y - p[j], 0.f)
              + fmaxf(v1.z - p[j], 0.f) + fmaxf(v1.w - p[j], 0.f)
              + fmaxf(v2.x - p[j], 0.f) + fmaxf(v2.y - p[j], 0.f)
              + fmaxf(v2.z - p[j], 0.f) + fmaxf(v2.w - p[j], 0.f);
    }
    #pragma unroll
    for (int o = 16; o > 0; o >>= 1)
        #pragma unroll
        for (int j = 0; j < 8; j++)
            s8[j] += __shfl_down_sync(0xffffffffu, s8[j], o);
    if (lane == 0) {
        #pragma unroll
        for (int j = 0; j < 8; j++) wr[warp][j] = s8[j];
    }
    __syncthreads();

    float ratio = 0.f;
    if (tid < 32) {
        const int rl = tid >> 3, j = tid & 7;
        const float rk = 1.f + wr[rl * 2][j] + wr[rl * 2 + 1][j];
        const float pj = refs[rl][j];
        float ps = 0.f;
        #pragma unroll
        for (int k = 0; k < 8; k++) ps += fmaxf(refs[rl][k] - pj, 0.f);
        ratio = (1.f + ps) / rk;
    }
    #pragma unroll
    for (int o = 16; o > 0; o >>= 1)
        ratio += __shfl_down_sync(0xffffffffu, ratio, o);

    // ================= Deterministic fixed-point accumulation ================
    if (tid == 0) {
        atomicAdd(&g_sum, (unsigned long long)llrintf(ratio * SCALE_F));
        __threadfence();
        const unsigned prev = atomicAdd(&g_done, 1);
        if (prev == NBLK - 1) {
            const unsigned long long tot = *((volatile unsigned long long*)&g_sum);
            out[0] = (float)(1.0 - ((double)tot * INV_SCALE) * (1.0 / 4096.0));
            g_sum  = 0;   // reset for next replay
            g_done = 0;
        }
    }
}

extern "C" void kernel_launch(void* const* d_in, const int* in_sizes, int n_in,
                              void* d_out, int out_size) {
    const float* fs = (const float*)d_in[0];
    const float* ft = (const float*)d_in[1];
    float* out = (float*)d_out;

    cudaFuncSetAttribute(fused_kernel,
                         cudaFuncAttributeMaxDynamicSharedMemorySize, SMEM_TOTAL);
    fused_kernel<<<dim3(16, 8), 256, SMEM_TOTAL>>>(fs, ft, out);
}